// round 12
// baseline (speedup 1.0000x reference)
#include <cuda_runtime.h>
#include <math.h>

#define SUBN  20
#define ENO   2000
#define INO   500
#define TDATA 10000
#define TSYN  200
#define THIST 50
#define CH    64
#define RING  512
#define TPAD  (TDATA + 2 * CH)

// ---------------- scratch (device globals; zero-initialized) ---------------
__device__ int   g_asgE[ENO];
__device__ int   g_asgI[INO];
__device__ float g_inE[SUBN * TDATA];
__device__ float g_inI[SUBN * TDATA];
__device__ float g_kS[SUBN * 2 * TSYN];
__device__ float g_kN[SUBN * 2 * TSYN];
__device__ float g_synST[SUBN * TPAD];          // syn_s - Theta_s, [s][t]
__device__ float g_synNT[SUBN * TPAD];          // syn_ns - Theta_ns

// ---------------- phase 1: one-hot -> assignment indices -------------------
__global__ void assign_kernel(const float* __restrict__ Ce,
                              const float* __restrict__ Ci) {
    int j = blockIdx.x * blockDim.x + threadIdx.x;
    if (j < ENO) {
        int s = 0;
        #pragma unroll
        for (int k = 0; k < SUBN; k++) if (Ce[k * ENO + j] > 0.5f) s = k;
        g_asgE[j] = s;
    }
    if (j < INO) {
        int s = 0;
        #pragma unroll
        for (int k = 0; k < SUBN; k++) if (Ci[k * INO + j] > 0.5f) s = k;
        g_asgI[j] = s;
    }
}

// ---------------- phase 2: sparse scatter-reduce S @ C^T -------------------
__global__ void reduce_kernel(const float* __restrict__ Se,
                              const float* __restrict__ Si, int T) {
    int t = blockIdx.x;
    if (t >= T) return;
    __shared__ float acc[2 * SUBN];
    int tid = threadIdx.x;
    if (tid < 2 * SUBN) acc[tid] = 0.0f;
    __syncthreads();
    for (int j = tid; j < ENO; j += blockDim.x) {
        float v = Se[(size_t)t * ENO + j];
        if (v != 0.0f) atomicAdd(&acc[g_asgE[j]], v);
    }
    for (int j = tid; j < INO; j += blockDim.x) {
        float v = Si[(size_t)t * INO + j];
        if (v != 0.0f) atomicAdd(&acc[SUBN + g_asgI[j]], v);
    }
    __syncthreads();
    if (tid < SUBN)            g_inE[tid * TDATA + t] = acc[tid];
    else if (tid < 2 * SUBN)   g_inI[(tid - SUBN) * TDATA + t] = acc[tid];
}

// ---------------- phase 3: build synaptic kernels ---------------------------
__global__ void kbuild_kernel(const float* __restrict__ Ws,  const float* __restrict__ Wn,
                              const float* __restrict__ TauS, const float* __restrict__ TauN,
                              const float* __restrict__ Ds,  const float* __restrict__ Dn) {
    int idx = blockIdx.x * blockDim.x + threadIdx.x;
    if (idx >= 2 * SUBN * 2 * TSYN) return;
    int k   = idx % TSYN;
    int c   = (idx / TSYN) % 2;
    int s   = (idx / (TSYN * 2)) % SUBN;
    int set = idx / (TSYN * 2 * SUBN);
    const float* W   = set ? Wn   : Ws;
    const float* Tau = set ? TauN : TauS;
    const float* D   = set ? Dn   : Ds;
    double ts = (double)k - exp((double)D[s * 2 + c]);
    if (ts < 0.0) ts = 0.0;
    double acc = 0.0;
    for (int b = 0; b < 3; b++) {
        double Tb = exp((double)Tau[b * 2 + c]);
        double u  = ts / Tb;
        acc += (double)W[s * 6 + b * 2 + c] * u * exp(-u);
    }
    float* out = set ? g_kN : g_kS;
    out[(s * 2 + c) * TSYN + k] = (float)acc;
}

// ---------------- phase 4: causal FIR; folds -Theta into the output --------
__global__ void conv_kernel(const float* __restrict__ ThS,
                            const float* __restrict__ ThN, int T) {
    const int i  = blockIdx.y;
    const int t0 = blockIdx.x * 256;
    __shared__ float she[256 + TSYN - 1];
    __shared__ float shi[256 + TSYN - 1];
    __shared__ float kse[TSYN], ksi[TSYN], kne[TSYN], kni[TSYN];
    int tid = threadIdx.x;
    for (int j = tid; j < 256 + TSYN - 1; j += 256) {
        int tg = t0 - (TSYN - 1) + j;
        bool ok = (tg >= 0 && tg < T);
        she[j] = ok ? g_inE[i * TDATA + tg] : 0.0f;
        shi[j] = ok ? g_inI[i * TDATA + tg] : 0.0f;
    }
    for (int k = tid; k < TSYN; k += 256) {
        kse[k] = g_kS[(i * 2 + 0) * TSYN + k];
        ksi[k] = g_kS[(i * 2 + 1) * TSYN + k];
        kne[k] = g_kN[(i * 2 + 0) * TSYN + k];
        kni[k] = g_kN[(i * 2 + 1) * TSYN + k];
    }
    __syncthreads();
    int t = t0 + tid;
    if (t < T) {
        float as = 0.0f, an = 0.0f;
        #pragma unroll 4
        for (int k = 0; k < TSYN; k++) {
            float xe = she[tid + (TSYN - 1) - k];
            float xi = shi[tid + (TSYN - 1) - k];
            as += xe * kse[k] + xi * ksi[k];
            an += xe * kne[k] + xi * kni[k];
        }
        g_synST[i * TPAD + t] = as - ThS[i];
        g_synNT[i * TPAD + t] = an - ThN[i];
    }
}

// ---------------- phase 5: warp-specialized scan, phased B/C/A loops --------
__device__ __forceinline__ float u2f_small(unsigned x) {  // exact for x < 2^23
    return __uint_as_float(0x4B000000u | x) - 8388608.0f;
}

#define MKCONST(tauH, tauP) {                                       \
    const float* taus_[2] = { tauH, tauP };                         \
    for (int ff = 0; ff < 2; ff++)                                  \
        for (int b = 0; b < 3; b++) {                               \
            double Tb  = exp((double)taus_[ff][b]);                 \
            double a   = exp(-1.0 / Tb);                            \
            double a49 = pow(a, (double)(THIST - 1));               \
            fa[ff*3+b]   = (float)a;                                \
            faot[ff*3+b] = (float)(a / Tb);                         \
            fa49[ff*3+b] = (float)a49;                              \
            fg49[ff*3+b] = (float)((double)(THIST - 1) / Tb * a49); \
        } }

// stage 65 rows: 64 chunk rows + 1 lookahead (each lane its own column only)
#define STAGE65(dst, src, gbase) {                                          \
    const float4* __restrict__ p_ = (const float4*)((src) + lane * TPAD + (gbase)); \
    _Pragma("unroll")                                                       \
    for (int q = 0; q < 16; q++) {                                          \
        float4 a_ = p_[q];                                                  \
        dst[4*q+0][lane] = a_.x; dst[4*q+1][lane] = a_.y;                   \
        dst[4*q+2][lane] = a_.z; dst[4*q+3][lane] = a_.w;                   \
    }                                                                       \
    dst[64][lane] = (src)[lane * TPAD + (gbase) + 64]; }

// packed sparse gather index construction (4 indices/word, pad = slot 31)
#define PACKIDX {                                                           \
    unsigned rem_ = row; int k = 0;                                         \
    while (rem_) {                                                          \
        int j = __ffs(rem_) - 1; rem_ &= rem_ - 1;                          \
        unsigned sh = 8u * (k & 3);                                         \
        unsigned cl = ~(0xFFu << sh);                                       \
        unsigned in = ((unsigned)j) << sh;                                  \
        switch (k >> 2) {                                                   \
            case 0: pw0 = (pw0 & cl) | in; break;                          \
            case 1: pw1 = (pw1 & cl) | in; break;                          \
            case 2: pw2 = (pw2 & cl) | in; break;                          \
            case 3: pw3 = (pw3 & cl) | in; break;                          \
            default: pw4 = (pw4 & cl) | in; break;                         \
        }                                                                   \
        k++;                                                                \
    } }

// conflict-free shared-array gather (bank j holds subunit j; slot 31 == 0)
#define GATHERS(shv, NW, c0_, c1_) {                                        \
    c0_ = shv[pw0 & 31] + shv[(pw0 >> 8) & 31];                             \
    c1_ = shv[(pw0 >> 16) & 31] + shv[pw0 >> 24];                           \
    if (NW > 1) {                                                           \
        c0_ += shv[pw1 & 31] + shv[(pw1 >> 8) & 31];                        \
        c1_ += shv[(pw1 >> 16) & 31] + shv[pw1 >> 24]; }                    \
    if (NW > 2) {                                                           \
        c0_ += shv[pw2 & 31] + shv[(pw2 >> 8) & 31];                        \
        c1_ += shv[(pw2 >> 16) & 31] + shv[pw2 >> 24]; }                    \
    if (NW > 3) {                                                           \
        c0_ += shv[pw3 & 31] + shv[(pw3 >> 8) & 31];                        \
        c1_ += shv[(pw3 >> 16) & 31] + shv[pw3 >> 24]; }                    \
    if (NW > 4) {                                                           \
        c0_ += shv[pw4 & 31] + shv[(pw4 >> 8) & 31];                        \
        c1_ += shv[(pw4 >> 16) & 31] + shv[pw4 >> 24]; } }

// ---- producer step, phased: B (gather/ballot) -> C (E, Ps) -> A (D, F) ----
// Invariants entering step t: Ps = syn(t)+Σw·F(t-1); Dc = D(t); F = F(t); m_prev = m(t-1).
#define ZSTEP(jj) {                                                         \
    /* B: the only loop-carried chain */                                    \
    unsigned mm = m_prev & row;                                             \
    float cs = (lut[0][mm & 31][lane] + lut[1][(mm >> 5) & 31][lane])       \
             + (lut[2][(mm >> 10) & 31][lane] + lut[3][(mm >> 15) & 31][lane]); \
    float ds = cs + Ps;                                                     \
    bool  z  = (ds >= 0.0f);                                                \
    unsigned m = __ballot_sync(0xFFFFFFFFu, z);                             \
    /* C: fold z(t) into E via precomputed D; next-step drive from old F */ \
    if (lane == 0) rm[t & (RING - 1)] = m;                                  \
    float zf = z ? 1.0f : 0.0f;                                             \
    float cf = u2f_small(__popc(m & row));                                  \
    E[0] = fmaf(fa[0], Dc[0], zf);                                          \
    E[1] = fmaf(fa[1], Dc[1], zf);                                          \
    E[2] = fmaf(fa[2], Dc[2], zf);                                          \
    E[3] = fmaf(fa[3], Dc[3], cf);                                          \
    E[4] = fmaf(fa[4], Dc[4], cf);                                          \
    E[5] = fmaf(fa[5], Dc[5], cf);                                          \
    if (act) Zp[lane] = zf;                                                 \
    Zp += SUBN;                                                             \
    float syn = shA[(jj) + 1][lane];                                        \
    float p0 = fmaf(w0_, F[0], syn);                                        \
    float p1 = fmaf(w1_, F[1], w2_ * F[2]);                                 \
    float p2 = fmaf(w3_, F[3], w4_ * F[4]);                                 \
    float p3 = w5_ * F[5];                                                  \
    Ps = (p0 + p1) + (p2 + p3);                                             \
    /* A: shadow for step t+1 (mold is 50-step-old data, off-chain) */      \
    unsigned mold = rm[(t + 1 + (RING - 50)) & (RING - 1)];                 \
    float zof = u2f_small((mold >> lane) & 1u);                             \
    float cof = u2f_small(__popc(mold & row));                              \
    Dc[0] = fmaf(-zof, fa49[0], E[0]);                                      \
    Dc[1] = fmaf(-zof, fa49[1], E[1]);                                      \
    Dc[2] = fmaf(-zof, fa49[2], E[2]);                                      \
    Dc[3] = fmaf(-cof, fa49[3], E[3]);                                      \
    Dc[4] = fmaf(-cof, fa49[4], E[4]);                                      \
    Dc[5] = fmaf(-cof, fa49[5], E[5]);                                      \
    F[0] = fmaf(fa[0], fmaf(-zof, fg49[0], F[0]), faot[0] * Dc[0]);         \
    F[1] = fmaf(fa[1], fmaf(-zof, fg49[1], F[1]), faot[1] * Dc[1]);         \
    F[2] = fmaf(fa[2], fmaf(-zof, fg49[2], F[2]), faot[2] * Dc[2]);         \
    F[3] = fmaf(fa[3], fmaf(-cof, fg49[3], F[3]), faot[3] * Dc[3]);         \
    F[4] = fmaf(fa[4], fmaf(-cof, fg49[4], F[4]), faot[4] * Dc[4]);         \
    F[5] = fmaf(fa[5], fmaf(-cof, fg49[5], F[5]), faot[5] * Dc[5]);         \
    m_prev = m; t++; }

// ---- consumer step, phased: B (tanh chain) -> C (E, Pn) -> A (D, F) -------
#define NSTEP(jj, NW) {                                                     \
    /* B: the only loop-carried chain */                                    \
    float c0, c1;                                                           \
    GATHERS(vexsh, NW, c0, c1)                                              \
    float dn = Pn + (c0 + c1);                                              \
    float e2 = __expf(2.0f * dn);                                           \
    float tr = fmaf(-2.0f, __frcp_rn(e2 + 1.0f), 1.0f);                     \
    float vex = tr * wns;                                                   \
    vexsh[lane] = vex;                                                      \
    if (lane == 0) Vp[0] = vex + Vo;                                        \
    Vp++;                                                                   \
    /* C */                                                                 \
    unsigned m_ = rm[t & (RING - 1)];                                       \
    float zf = u2f_small((m_ >> lane) & 1u);                                \
    float cf = u2f_small(__popc(m_ & row));                                 \
    E[0] = fmaf(fa[0], Dc[0], zf);                                          \
    E[1] = fmaf(fa[1], Dc[1], zf);                                          \
    E[2] = fmaf(fa[2], Dc[2], zf);                                          \
    E[3] = fmaf(fa[3], Dc[3], cf);                                          \
    E[4] = fmaf(fa[4], Dc[4], cf);                                          \
    E[5] = fmaf(fa[5], Dc[5], cf);                                          \
    float syn = shB[(jj) + 1][lane];                                        \
    float p0 = fmaf(w0_, F[0], syn);                                        \
    float p1 = fmaf(w1_, F[1], w2_ * F[2]);                                 \
    float p2 = fmaf(w3_, F[3], w4_ * F[4]);                                 \
    float p3 = w5_ * F[5];                                                  \
    Pn = (p0 + p1) + (p2 + p3);                                             \
    /* A */                                                                 \
    unsigned mold_ = rm[(t + 1 + (RING - 50)) & (RING - 1)];                \
    float zof = u2f_small((mold_ >> lane) & 1u);                            \
    float cof = u2f_small(__popc(mold_ & row));                             \
    Dc[0] = fmaf(-zof, fa49[0], E[0]);                                      \
    Dc[1] = fmaf(-zof, fa49[1], E[1]);                                      \
    Dc[2] = fmaf(-zof, fa49[2], E[2]);                                      \
    Dc[3] = fmaf(-cof, fa49[3], E[3]);                                      \
    Dc[4] = fmaf(-cof, fa49[4], E[4]);                                      \
    Dc[5] = fmaf(-cof, fa49[5], E[5]);                                      \
    F[0] = fmaf(fa[0], fmaf(-zof, fg49[0], F[0]), faot[0] * Dc[0]);         \
    F[1] = fmaf(fa[1], fmaf(-zof, fg49[1], F[1]), faot[1] * Dc[1]);         \
    F[2] = fmaf(fa[2], fmaf(-zof, fg49[2], F[2]), faot[2] * Dc[2]);         \
    F[3] = fmaf(fa[3], fmaf(-cof, fg49[3], F[3]), faot[3] * Dc[3]);         \
    F[4] = fmaf(fa[4], fmaf(-cof, fg49[4], F[4]), faot[4] * Dc[4]);         \
    F[5] = fmaf(fa[5], fmaf(-cof, fg49[5], F[5]), faot[5] * Dc[5]);         \
    t++; }

#define NSRUN(NW) {                                                         \
    for (int c = 0; c < nfull; c++) {                                       \
        int t0 = c << 6;                                                    \
        while (s_prod < t0 + CH) {}                                         \
        if (lane == 0) s_cons = t0;                                         \
        _Pragma("unroll 4")                                                 \
        for (int j = 0; j < CH; j++) { NSTEP(j, NW) }                       \
        if (act) STAGE65(shB, g_synNT, t0 + CH)                             \
    }                                                                       \
    while (s_prod < T) {}                                                   \
    if (lane == 0) s_cons = nfull << 6;                                     \
    for (int j = 0; j < rem; j++) { NSTEP(j, NW) } }

__global__ void __launch_bounds__(64, 1)
scan_kernel(const float* __restrict__ Cden,
            const float* __restrict__ WsH, const float* __restrict__ WnH,
            const float* __restrict__ TsH, const float* __restrict__ TnH,
            const float* __restrict__ WsP, const float* __restrict__ WnP,
            const float* __restrict__ TsP, const float* __restrict__ TnP,
            const float* __restrict__ WsSub, const float* __restrict__ WnSub,
            const float* __restrict__ Vop,
            float* __restrict__ V, float* __restrict__ Z, int T)
{
    const int tid  = threadIdx.x;
    const int lane = tid & 31;
    const int wrp  = tid >> 5;
    const bool act = lane < SUBN;

    __shared__ float lut[4][32][32];                 // 16 KB spiking-coupling LUT
    __shared__ float shA[CH + 1][32];                // producer syn buffer
    __shared__ float shB[CH + 1][32];                // consumer syn buffer
    __shared__ volatile unsigned rm[RING];           // mask ring
    __shared__ volatile float vexsh[32];             // ns exchange: tanh*Wns
    __shared__ volatile int s_prod, s_cons;

    for (int x = tid; x < RING; x += 64) rm[x] = 0u;
    for (int x = tid; x < (CH + 1) * 32; x += 64) {
        ((float*)shA)[x] = 0.0f;
        ((float*)shB)[x] = 0.0f;
    }
    if (wrp == 1) vexsh[lane] = 0.0f;
    if (tid == 0) { s_prod = 0; s_cons = 0; }

    unsigned row = 0;
    if (act) {
        #pragma unroll
        for (int j = 0; j < SUBN; j++)
            if (Cden[lane * SUBN + j] != 0.0f) row |= (1u << j);
    }

    if (wrp == 0) {
        // 4 x 5-bit spiking-coupling LUT (each lane fills its own column)
        for (int g = 0; g < 4; g++)
            for (int v = 0; v < 32; v++) {
                float s = 0.0f;
                #pragma unroll
                for (int b = 0; b < 5; b++) {
                    int j = g * 5 + b;
                    if (j < SUBN && ((v >> b) & 1) && ((row >> j) & 1))
                        s += WsSub[j];
                }
                lut[g][v][lane] = s;
            }
    }

    unsigned pw0 = 0x1F1F1F1Fu, pw1 = 0x1F1F1F1Fu, pw2 = 0x1F1F1F1Fu,
             pw3 = 0x1F1F1F1Fu, pw4 = 0x1F1F1F1Fu;
    PACKIDX
    int kmax = (int)__reduce_max_sync(0xFFFFFFFFu, (unsigned)__popc(row));

    __syncthreads();

    const int nfull = T >> 6;
    const int rem   = T & (CH - 1);

    if (wrp == 0) {
        // ======================= z warp (producer) ==========================
        float fa[6], faot[6], fa49[6], fg49[6];
        MKCONST(TsH, TsP);
        float F[6], E[6], Dc[6];
        #pragma unroll
        for (int f = 0; f < 6; f++) { F[f] = 0.0f; E[f] = 0.0f; Dc[f] = 0.0f; }
        float w0_ = 0, w1_ = 0, w2_ = 0, w3_ = 0, w4_ = 0, w5_ = 0;
        if (act) {
            w0_ = WsH[lane * 3 + 0]; w1_ = WsH[lane * 3 + 1]; w2_ = WsH[lane * 3 + 2];
            w3_ = WsP[lane * 3 + 0]; w4_ = WsP[lane * 3 + 1]; w5_ = WsP[lane * 3 + 2];
        }
        if (act) STAGE65(shA, g_synST, 0)

        float Ps = shA[0][lane];
        if (!act) Ps = 0.0f;
        unsigned m_prev = 0;
        float* Zp = Z;
        int t = 0;

        for (int c = 0; c < nfull; c++) {
            int t0 = c << 6;
            while (s_cons + (RING - 2 * CH) < t0) {}          // ring gate
            #pragma unroll 4
            for (int j = 0; j < CH; j++) { ZSTEP(j) }
            __threadfence_block();
            if (lane == 0) s_prod = t0 + CH;
            if (act) STAGE65(shA, g_synST, t0 + CH)           // next chunk
        }
        for (int j = 0; j < rem; j++) { ZSTEP(j) }
        __threadfence_block();
        if (lane == 0) s_prod = T;
    } else {
        // ======================= ns warp (consumer) =========================
        float fa[6], faot[6], fa49[6], fg49[6];
        MKCONST(TnH, TnP);
        float F[6], E[6], Dc[6];
        #pragma unroll
        for (int f = 0; f < 6; f++) { F[f] = 0.0f; E[f] = 0.0f; Dc[f] = 0.0f; }
        float w0_ = 0, w1_ = 0, w2_ = 0, w3_ = 0, w4_ = 0, w5_ = 0, wns = 0;
        if (act) {
            w0_ = WnH[lane * 3 + 0]; w1_ = WnH[lane * 3 + 1]; w2_ = WnH[lane * 3 + 2];
            w3_ = WnP[lane * 3 + 0]; w4_ = WnP[lane * 3 + 1]; w5_ = WnP[lane * 3 + 2];
            wns = WnSub[lane];
        }
        const float Vo = Vop[0];

        if (act) STAGE65(shB, g_synNT, 0)

        float Pn  = shB[0][lane];
        float* Vp = V;
        int t = 0;

        if (kmax <= 8)       { NSRUN(2) }
        else if (kmax <= 12) { NSRUN(3) }
        else                 { NSRUN(5) }
    }
}

// ---------------- launch ----------------------------------------------------
extern "C" void kernel_launch(void* const* d_in, const int* in_sizes, int n_in,
                              void* d_out, int out_size) {
    const float* Se      = (const float*)d_in[0];
    const float* Si      = (const float*)d_in[1];
    const float* Cden    = (const float*)d_in[2];
    const float* Ce      = (const float*)d_in[3];
    const float* Ci      = (const float*)d_in[4];
    const float* WsSyn   = (const float*)d_in[5];
    const float* WnSyn   = (const float*)d_in[6];
    const float* TauSsyn = (const float*)d_in[7];
    const float* TauNsyn = (const float*)d_in[8];
    const float* DsSyn   = (const float*)d_in[9];
    const float* DnSyn   = (const float*)d_in[10];
    const float* WsH     = (const float*)d_in[11];
    const float* WnH     = (const float*)d_in[12];
    const float* TsH     = (const float*)d_in[13];
    const float* TnH     = (const float*)d_in[14];
    const float* WsP     = (const float*)d_in[15];
    const float* WnP     = (const float*)d_in[16];
    const float* TsP     = (const float*)d_in[17];
    const float* TnP     = (const float*)d_in[18];
    const float* WsSub   = (const float*)d_in[19];
    const float* WnSub   = (const float*)d_in[20];
    const float* ThS     = (const float*)d_in[21];
    const float* ThN     = (const float*)d_in[22];
    const float* Vo      = (const float*)d_in[23];

    int T = in_sizes[0] / ENO;          // 10000
    if (T > TDATA) T = TDATA;
    float* out = (float*)d_out;
    float* V = out;
    float* Z = out + T;

    assign_kernel<<<(ENO + 255) / 256, 256>>>(Ce, Ci);
    reduce_kernel<<<T, 256>>>(Se, Si, T);
    kbuild_kernel<<<(2 * SUBN * 2 * TSYN + 255) / 256, 256>>>(WsSyn, WnSyn, TauSsyn, TauNsyn, DsSyn, DnSyn);
    dim3 cg((T + 255) / 256, SUBN);
    conv_kernel<<<cg, 256>>>(ThS, ThN, T);
    scan_kernel<<<1, 64>>>(Cden, WsH, WnH, TsH, TnH, WsP, WnP, TsP, TnP,
                           WsSub, WnSub, Vo, V, Z, T);
}

// round 13
// speedup vs baseline: 1.3485x; 1.3485x over previous
#include <cuda_runtime.h>
#include <math.h>

#define SUBN  20
#define ENO   2000
#define INO   500
#define TDATA 10000
#define TSYN  200
#define THIST 50
#define CH    64
#define RING  512
#define TPAD  (TDATA + 2 * CH)

// ---------------- scratch (device globals; zero-initialized) ---------------
__device__ int   g_asgE[ENO];
__device__ int   g_asgI[INO];
__device__ float g_inE[SUBN * TDATA];
__device__ float g_inI[SUBN * TDATA];
__device__ float g_kS[SUBN * 2 * TSYN];
__device__ float g_kN[SUBN * 2 * TSYN];
__device__ float g_synST[SUBN * TPAD];          // syn_s - Theta_s, [s][t]
__device__ float g_synNT[SUBN * TPAD];          // syn_ns - Theta_ns

// ---------------- phase 1: one-hot -> assignment indices -------------------
__global__ void assign_kernel(const float* __restrict__ Ce,
                              const float* __restrict__ Ci) {
    int j = blockIdx.x * blockDim.x + threadIdx.x;
    if (j < ENO) {
        int s = 0;
        #pragma unroll
        for (int k = 0; k < SUBN; k++) if (Ce[k * ENO + j] > 0.5f) s = k;
        g_asgE[j] = s;
    }
    if (j < INO) {
        int s = 0;
        #pragma unroll
        for (int k = 0; k < SUBN; k++) if (Ci[k * INO + j] > 0.5f) s = k;
        g_asgI[j] = s;
    }
}

// ---------------- phase 2: sparse scatter-reduce S @ C^T -------------------
__global__ void reduce_kernel(const float* __restrict__ Se,
                              const float* __restrict__ Si, int T) {
    int t = blockIdx.x;
    if (t >= T) return;
    __shared__ float acc[2 * SUBN];
    int tid = threadIdx.x;
    if (tid < 2 * SUBN) acc[tid] = 0.0f;
    __syncthreads();
    for (int j = tid; j < ENO; j += blockDim.x) {
        float v = Se[(size_t)t * ENO + j];
        if (v != 0.0f) atomicAdd(&acc[g_asgE[j]], v);
    }
    for (int j = tid; j < INO; j += blockDim.x) {
        float v = Si[(size_t)t * INO + j];
        if (v != 0.0f) atomicAdd(&acc[SUBN + g_asgI[j]], v);
    }
    __syncthreads();
    if (tid < SUBN)            g_inE[tid * TDATA + t] = acc[tid];
    else if (tid < 2 * SUBN)   g_inI[(tid - SUBN) * TDATA + t] = acc[tid];
}

// ---------------- phase 3: build synaptic kernels ---------------------------
__global__ void kbuild_kernel(const float* __restrict__ Ws,  const float* __restrict__ Wn,
                              const float* __restrict__ TauS, const float* __restrict__ TauN,
                              const float* __restrict__ Ds,  const float* __restrict__ Dn) {
    int idx = blockIdx.x * blockDim.x + threadIdx.x;
    if (idx >= 2 * SUBN * 2 * TSYN) return;
    int k   = idx % TSYN;
    int c   = (idx / TSYN) % 2;
    int s   = (idx / (TSYN * 2)) % SUBN;
    int set = idx / (TSYN * 2 * SUBN);
    const float* W   = set ? Wn   : Ws;
    const float* Tau = set ? TauN : TauS;
    const float* D   = set ? Dn   : Ds;
    double ts = (double)k - exp((double)D[s * 2 + c]);
    if (ts < 0.0) ts = 0.0;
    double acc = 0.0;
    for (int b = 0; b < 3; b++) {
        double Tb = exp((double)Tau[b * 2 + c]);
        double u  = ts / Tb;
        acc += (double)W[s * 6 + b * 2 + c] * u * exp(-u);
    }
    float* out = set ? g_kN : g_kS;
    out[(s * 2 + c) * TSYN + k] = (float)acc;
}

// ---------------- phase 4: causal FIR; folds -Theta into the output --------
__global__ void conv_kernel(const float* __restrict__ ThS,
                            const float* __restrict__ ThN, int T) {
    const int i  = blockIdx.y;
    const int t0 = blockIdx.x * 256;
    __shared__ float she[256 + TSYN - 1];
    __shared__ float shi[256 + TSYN - 1];
    __shared__ float kse[TSYN], ksi[TSYN], kne[TSYN], kni[TSYN];
    int tid = threadIdx.x;
    for (int j = tid; j < 256 + TSYN - 1; j += 256) {
        int tg = t0 - (TSYN - 1) + j;
        bool ok = (tg >= 0 && tg < T);
        she[j] = ok ? g_inE[i * TDATA + tg] : 0.0f;
        shi[j] = ok ? g_inI[i * TDATA + tg] : 0.0f;
    }
    for (int k = tid; k < TSYN; k += 256) {
        kse[k] = g_kS[(i * 2 + 0) * TSYN + k];
        ksi[k] = g_kS[(i * 2 + 1) * TSYN + k];
        kne[k] = g_kN[(i * 2 + 0) * TSYN + k];
        kni[k] = g_kN[(i * 2 + 1) * TSYN + k];
    }
    __syncthreads();
    int t = t0 + tid;
    if (t < T) {
        float as = 0.0f, an = 0.0f;
        #pragma unroll 4
        for (int k = 0; k < TSYN; k++) {
            float xe = she[tid + (TSYN - 1) - k];
            float xi = shi[tid + (TSYN - 1) - k];
            as += xe * kse[k] + xi * ksi[k];
            an += xe * kne[k] + xi * kni[k];
        }
        g_synST[i * TPAD + t] = as - ThS[i];
        g_synNT[i * TPAD + t] = an - ThN[i];
    }
}

// ---------------- phase 5: warp-specialized scan (R4 + f32x2 filters) -------
typedef unsigned long long u64;

__device__ __forceinline__ float u2f_small(unsigned x) {  // exact for x < 2^23
    return __uint_as_float(0x4B000000u | x) - 8388608.0f;
}
__device__ __forceinline__ u64 pk2(float lo, float hi) {
    u64 r; asm("mov.b64 %0, {%1, %2};" : "=l"(r) : "f"(lo), "f"(hi)); return r;
}
__device__ __forceinline__ void upk2(float& lo, float& hi, u64 v) {
    asm("mov.b64 {%0, %1}, %2;" : "=f"(lo), "=f"(hi) : "l"(v));
}
__device__ __forceinline__ u64 fma2(u64 a, u64 b, u64 c) {
    u64 r; asm("fma.rn.f32x2 %0, %1, %2, %3;" : "=l"(r) : "l"(a), "l"(b), "l"(c)); return r;
}
__device__ __forceinline__ u64 mul2(u64 a, u64 b) {
    u64 r; asm("mul.rn.f32x2 %0, %1, %2;" : "=l"(r) : "l"(a), "l"(b)); return r;
}

#define MKCONST(tauH, tauP) {                                       \
    const float* taus_[2] = { tauH, tauP };                         \
    for (int ff = 0; ff < 2; ff++)                                  \
        for (int b = 0; b < 3; b++) {                               \
            double Tb  = exp((double)taus_[ff][b]);                 \
            double a   = exp(-1.0 / Tb);                            \
            double a49 = pow(a, (double)(THIST - 1));               \
            fa[ff*3+b]   = (float)a;                                \
            faot[ff*3+b] = (float)(a / Tb);                         \
            fa49[ff*3+b] = (float)a49;                              \
            fg49[ff*3+b] = (float)((double)(THIST - 1) / Tb * a49); \
        } }

// pack scalar filter constants into 3 f32x2 pairs (negated where needed)
#define PACKCONST {                                                 \
    for (int p = 0; p < 3; p++) {                                   \
        fa2[p]    = pk2(fa[2*p],    fa[2*p+1]);                     \
        faot2[p]  = pk2(faot[2*p],  faot[2*p+1]);                   \
        fa49n2[p] = pk2(-fa49[2*p], -fa49[2*p+1]);                  \
        fg49n2[p] = pk2(-fg49[2*p], -fg49[2*p+1]);                  \
        E2[p] = pk2(0.0f, 0.0f);                                    \
        F2[p] = pk2(0.0f, 0.0f);                                    \
    } }

// packed filter update: D = E + xo*(-fa49); F = fa*(F + xo*(-fg49)) + faot*D; E = fa*D + x
#define FUPD2(p, x2_, xo2_) {                                       \
    u64 D_ = fma2(xo2_, fa49n2[p], E2[p]);                          \
    F2[p] = fma2(fa2[p], fma2(xo2_, fg49n2[p], F2[p]), mul2(faot2[p], D_)); \
    E2[p] = fma2(fa2[p], D_, x2_); }

// packed drive: syn + sum_f w_f * F_f
#define DRIVE2(dst_, syn_) {                                        \
    u64 acc_ = mul2(w01, F2[0]);                                    \
    acc_ = fma2(w23, F2[1], acc_);                                  \
    acc_ = fma2(w45, F2[2], acc_);                                  \
    float alo_, ahi_; upk2(alo_, ahi_, acc_);                       \
    dst_ = ((syn_) + alo_) + ahi_; }

// stage 65 rows: 64 chunk rows + 1 lookahead (each lane its own column only)
#define STAGE65(dst, src, gbase) {                                          \
    const float4* __restrict__ p_ = (const float4*)((src) + lane * TPAD + (gbase)); \
    _Pragma("unroll")                                                       \
    for (int q = 0; q < 16; q++) {                                          \
        float4 a_ = p_[q];                                                  \
        dst[4*q+0][lane] = a_.x; dst[4*q+1][lane] = a_.y;                   \
        dst[4*q+2][lane] = a_.z; dst[4*q+3][lane] = a_.w;                   \
    }                                                                       \
    dst[64][lane] = (src)[lane * TPAD + (gbase) + 64]; }

// packed sparse gather index construction (4 indices/word, pad = lane 31)
#define PACKIDX {                                                           \
    unsigned rem_ = row; int k = 0;                                         \
    while (rem_) {                                                          \
        int j = __ffs(rem_) - 1; rem_ &= rem_ - 1;                          \
        unsigned sh = 8u * (k & 3);                                         \
        unsigned cl = ~(0xFFu << sh);                                       \
        unsigned in = ((unsigned)j) << sh;                                  \
        switch (k >> 2) {                                                   \
            case 0: pw0 = (pw0 & cl) | in; break;                          \
            case 1: pw1 = (pw1 & cl) | in; break;                          \
            case 2: pw2 = (pw2 & cl) | in; break;                          \
            case 3: pw3 = (pw3 & cl) | in; break;                          \
            default: pw4 = (pw4 & cl) | in; break;                         \
        }                                                                   \
        k++;                                                                \
    } }

// sparse shuffle gather of per-lane exported value `vv` into c0_,c1_
#define GATHER(vv, NW, c0_, c1_) {                                          \
    c0_ = __shfl_sync(0xFFFFFFFFu, vv, pw0 & 31)                            \
        + __shfl_sync(0xFFFFFFFFu, vv, (pw0 >> 8) & 31);                    \
    c1_ = __shfl_sync(0xFFFFFFFFu, vv, (pw0 >> 16) & 31)                    \
        + __shfl_sync(0xFFFFFFFFu, vv, pw0 >> 24);                          \
    if (NW > 1) {                                                           \
        c0_ += __shfl_sync(0xFFFFFFFFu, vv, pw1 & 31)                       \
             + __shfl_sync(0xFFFFFFFFu, vv, (pw1 >> 8) & 31);               \
        c1_ += __shfl_sync(0xFFFFFFFFu, vv, (pw1 >> 16) & 31)               \
             + __shfl_sync(0xFFFFFFFFu, vv, pw1 >> 24); }                   \
    if (NW > 2) {                                                           \
        c0_ += __shfl_sync(0xFFFFFFFFu, vv, pw2 & 31)                       \
             + __shfl_sync(0xFFFFFFFFu, vv, (pw2 >> 8) & 31);               \
        c1_ += __shfl_sync(0xFFFFFFFFu, vv, (pw2 >> 16) & 31)               \
             + __shfl_sync(0xFFFFFFFFu, vv, pw2 >> 24); }                   \
    if (NW > 3) {                                                           \
        c0_ += __shfl_sync(0xFFFFFFFFu, vv, pw3 & 31)                       \
             + __shfl_sync(0xFFFFFFFFu, vv, (pw3 >> 8) & 31);               \
        c1_ += __shfl_sync(0xFFFFFFFFu, vv, (pw3 >> 16) & 31)               \
             + __shfl_sync(0xFFFFFFFFu, vv, pw3 >> 24); }                   \
    if (NW > 4) {                                                           \
        c0_ += __shfl_sync(0xFFFFFFFFu, vv, pw4 & 31)                       \
             + __shfl_sync(0xFFFFFFFFu, vv, (pw4 >> 8) & 31);               \
        c1_ += __shfl_sync(0xFFFFFFFFu, vv, (pw4 >> 16) & 31)               \
             + __shfl_sync(0xFFFFFFFFu, vv, pw4 >> 24); } }

// ---- producer (z) inner step: R4 structure, f32x2 filter math --------------
#define ZSTEP(jj) {                                                         \
    unsigned mm = m_prev & row;                                             \
    float cs = (lut[0][mm & 31][lane] + lut[1][(mm >> 5) & 31][lane])       \
             + (lut[2][(mm >> 10) & 31][lane] + lut[3][(mm >> 15) & 31][lane]); \
    float ds = cs + Ps;                                                     \
    bool  z  = (ds >= 0.0f);                                                \
    unsigned m = __ballot_sync(0xFFFFFFFFu, z);                             \
    if (lane == 0) rm[t & (RING - 1)] = m;                                  \
    unsigned mold = rm[(t + (RING - 50)) & (RING - 1)];                     \
    float zf = z ? 1.0f : 0.0f;                                             \
    if (act) Zp[lane] = zf;                                                 \
    Zp += SUBN;                                                             \
    float cf  = u2f_small(__popc(m & row));                                 \
    float zof = u2f_small((mold >> lane) & 1u);                             \
    float cof = u2f_small(__popc(mold & row));                              \
    u64 x01 = pk2(zf, zf), x23 = pk2(zf, cf), x45 = pk2(cf, cf);            \
    u64 o01 = pk2(zof, zof), o23 = pk2(zof, cof), o45 = pk2(cof, cof);      \
    FUPD2(0, x01, o01) FUPD2(1, x23, o23) FUPD2(2, x45, o45)                \
    float syn = shA[(jj) + 1][lane];                                        \
    DRIVE2(Ps, syn)                                                         \
    m_prev = m; t++; }

// ---- consumer (ns) inner step: R4 structure, f32x2 filter math -------------
#define NSTEP(jj, NW) {                                                     \
    unsigned m_    = rm[t & (RING - 1)];                                    \
    unsigned mold_ = rm[(t + (RING - 50)) & (RING - 1)];                    \
    float c0, c1;                                                           \
    GATHER(vex, NW, c0, c1)                                                 \
    float dn = Pn + (c0 + c1);                                              \
    float e2 = __expf(2.0f * dn);                                           \
    float tr = 1.0f - __fdividef(2.0f, e2 + 1.0f);                          \
    vex = tr * wns;                                                         \
    if (lane == 0) Vp[0] = vex + Vo;                                        \
    Vp++;                                                                   \
    float zf  = u2f_small((m_ >> lane) & 1u);                               \
    float cf  = u2f_small(__popc(m_ & row));                                \
    float zof = u2f_small((mold_ >> lane) & 1u);                            \
    float cof = u2f_small(__popc(mold_ & row));                             \
    u64 x01 = pk2(zf, zf), x23 = pk2(zf, cf), x45 = pk2(cf, cf);            \
    u64 o01 = pk2(zof, zof), o23 = pk2(zof, cof), o45 = pk2(cof, cof);      \
    FUPD2(0, x01, o01) FUPD2(1, x23, o23) FUPD2(2, x45, o45)                \
    float syn = shB[(jj) + 1][lane];                                        \
    DRIVE2(Pn, syn)                                                         \
    t++; }

#define NSRUN(NW) {                                                         \
    for (int c = 0; c < nfull; c++) {                                       \
        int t0 = c << 6;                                                    \
        while (s_prod < t0 + CH) {}                                         \
        if (lane == 0) s_cons = t0;                                         \
        _Pragma("unroll 4")                                                 \
        for (int j = 0; j < CH; j++) { NSTEP(j, NW) }                       \
        if (act) STAGE65(shB, g_synNT, t0 + CH)                             \
    }                                                                       \
    while (s_prod < T) {}                                                   \
    if (lane == 0) s_cons = nfull << 6;                                     \
    for (int j = 0; j < rem; j++) { NSTEP(j, NW) } }

__global__ void __launch_bounds__(64, 1)
scan_kernel(const float* __restrict__ Cden,
            const float* __restrict__ WsH, const float* __restrict__ WnH,
            const float* __restrict__ TsH, const float* __restrict__ TnH,
            const float* __restrict__ WsP, const float* __restrict__ WnP,
            const float* __restrict__ TsP, const float* __restrict__ TnP,
            const float* __restrict__ WsSub, const float* __restrict__ WnSub,
            const float* __restrict__ Vop,
            float* __restrict__ V, float* __restrict__ Z, int T)
{
    const int tid  = threadIdx.x;
    const int lane = tid & 31;
    const int wrp  = tid >> 5;
    const bool act = lane < SUBN;

    __shared__ float lut[4][32][32];                 // 16 KB spiking-coupling LUT
    __shared__ float shA[CH + 1][32];                // producer syn buffer
    __shared__ float shB[CH + 1][32];                // consumer syn buffer
    __shared__ volatile unsigned rm[RING];           // mask ring
    __shared__ volatile int s_prod, s_cons;

    for (int x = tid; x < RING; x += 64) rm[x] = 0u;
    for (int x = tid; x < (CH + 1) * 32; x += 64) {
        ((float*)shA)[x] = 0.0f;
        ((float*)shB)[x] = 0.0f;
    }
    if (tid == 0) { s_prod = 0; s_cons = 0; }

    unsigned row = 0;
    if (act) {
        #pragma unroll
        for (int j = 0; j < SUBN; j++)
            if (Cden[lane * SUBN + j] != 0.0f) row |= (1u << j);
    }

    if (wrp == 0) {
        // 4 x 5-bit spiking-coupling LUT (each lane fills its own column)
        for (int g = 0; g < 4; g++)
            for (int v = 0; v < 32; v++) {
                float s = 0.0f;
                #pragma unroll
                for (int b = 0; b < 5; b++) {
                    int j = g * 5 + b;
                    if (j < SUBN && ((v >> b) & 1) && ((row >> j) & 1))
                        s += WsSub[j];
                }
                lut[g][v][lane] = s;
            }
    }

    unsigned pw0 = 0x1F1F1F1Fu, pw1 = 0x1F1F1F1Fu, pw2 = 0x1F1F1F1Fu,
             pw3 = 0x1F1F1F1Fu, pw4 = 0x1F1F1F1Fu;
    PACKIDX
    int kmax = (int)__reduce_max_sync(0xFFFFFFFFu, (unsigned)__popc(row));

    __syncthreads();

    const int nfull = T >> 6;
    const int rem   = T & (CH - 1);

    if (wrp == 0) {
        // ======================= z warp (producer) ==========================
        float fa[6], faot[6], fa49[6], fg49[6];
        MKCONST(TsH, TsP);
        u64 fa2[3], faot2[3], fa49n2[3], fg49n2[3], E2[3], F2[3];
        PACKCONST
        float w0_ = 0, w1_ = 0, w2_ = 0, w3_ = 0, w4_ = 0, w5_ = 0;
        if (act) {
            w0_ = WsH[lane * 3 + 0]; w1_ = WsH[lane * 3 + 1]; w2_ = WsH[lane * 3 + 2];
            w3_ = WsP[lane * 3 + 0]; w4_ = WsP[lane * 3 + 1]; w5_ = WsP[lane * 3 + 2];
        }
        u64 w01 = pk2(w0_, w1_), w23 = pk2(w2_, w3_), w45 = pk2(w4_, w5_);
        if (act) STAGE65(shA, g_synST, 0)

        float Ps = shA[0][lane];
        if (!act) Ps = 0.0f;
        unsigned m_prev = 0;
        float* Zp = Z;
        int t = 0;

        for (int c = 0; c < nfull; c++) {
            int t0 = c << 6;
            while (s_cons + (RING - 2 * CH) < t0) {}          // ring gate
            #pragma unroll 4
            for (int j = 0; j < CH; j++) { ZSTEP(j) }
            __threadfence_block();
            if (lane == 0) s_prod = t0 + CH;
            if (act) STAGE65(shA, g_synST, t0 + CH)           // next chunk
        }
        for (int j = 0; j < rem; j++) { ZSTEP(j) }
        __threadfence_block();
        if (lane == 0) s_prod = T;
    } else {
        // ======================= ns warp (consumer) =========================
        float fa[6], faot[6], fa49[6], fg49[6];
        MKCONST(TnH, TnP);
        u64 fa2[3], faot2[3], fa49n2[3], fg49n2[3], E2[3], F2[3];
        PACKCONST
        float w0_ = 0, w1_ = 0, w2_ = 0, w3_ = 0, w4_ = 0, w5_ = 0, wns = 0;
        if (act) {
            w0_ = WnH[lane * 3 + 0]; w1_ = WnH[lane * 3 + 1]; w2_ = WnH[lane * 3 + 2];
            w3_ = WnP[lane * 3 + 0]; w4_ = WnP[lane * 3 + 1]; w5_ = WnP[lane * 3 + 2];
            wns = WnSub[lane];
        }
        u64 w01 = pk2(w0_, w1_), w23 = pk2(w2_, w3_), w45 = pk2(w4_, w5_);
        const float Vo = Vop[0];

        if (act) STAGE65(shB, g_synNT, 0)

        float Pn  = shB[0][lane];
        float vex = 0.0f;
        float* Vp = V;
        int t = 0;

        if (kmax <= 8)       { NSRUN(2) }
        else if (kmax <= 12) { NSRUN(3) }
        else                 { NSRUN(5) }
    }
}

// ---------------- launch ----------------------------------------------------
extern "C" void kernel_launch(void* const* d_in, const int* in_sizes, int n_in,
                              void* d_out, int out_size) {
    const float* Se      = (const float*)d_in[0];
    const float* Si      = (const float*)d_in[1];
    const float* Cden    = (const float*)d_in[2];
    const float* Ce      = (const float*)d_in[3];
    const float* Ci      = (const float*)d_in[4];
    const float* WsSyn   = (const float*)d_in[5];
    const float* WnSyn   = (const float*)d_in[6];
    const float* TauSsyn = (const float*)d_in[7];
    const float* TauNsyn = (const float*)d_in[8];
    const float* DsSyn   = (const float*)d_in[9];
    const float* DnSyn   = (const float*)d_in[10];
    const float* WsH     = (const float*)d_in[11];
    const float* WnH     = (const float*)d_in[12];
    const float* TsH     = (const float*)d_in[13];
    const float* TnH     = (const float*)d_in[14];
    const float* WsP     = (const float*)d_in[15];
    const float* WnP     = (const float*)d_in[16];
    const float* TsP     = (const float*)d_in[17];
    const float* TnP     = (const float*)d_in[18];
    const float* WsSub   = (const float*)d_in[19];
    const float* WnSub   = (const float*)d_in[20];
    const float* ThS     = (const float*)d_in[21];
    const float* ThN     = (const float*)d_in[22];
    const float* Vo      = (const float*)d_in[23];

    int T = in_sizes[0] / ENO;          // 10000
    if (T > TDATA) T = TDATA;
    float* out = (float*)d_out;
    float* V = out;
    float* Z = out + T;

    assign_kernel<<<(ENO + 255) / 256, 256>>>(Ce, Ci);
    reduce_kernel<<<T, 256>>>(Se, Si, T);
    kbuild_kernel<<<(2 * SUBN * 2 * TSYN + 255) / 256, 256>>>(WsSyn, WnSyn, TauSsyn, TauNsyn, DsSyn, DnSyn);
    dim3 cg((T + 255) / 256, SUBN);
    conv_kernel<<<cg, 256>>>(ThS, ThN, T);
    scan_kernel<<<1, 64>>>(Cden, WsH, WnH, TsH, TnH, WsP, WnP, TsP, TnP,
                           WsSub, WnSub, Vo, V, Z, T);
}